// round 1
// baseline (speedup 1.0000x reference)
#include <cuda_runtime.h>
#include <math.h>

#define N_NODES 50000
#define NRELS   8
#define HD      64

// Scratch (allocation-free: __device__ globals)
__device__ double g_acc[2];                 // [0]=node part, [1]=edge part
__device__ float  g_Wt[28 * 64];            // 28 weight rows of length 64
__device__ float4 g_vtab[N_NODES * NRELS];  // per-(node, rel): (v0, v1, vb, 0)

// ---------------------------------------------------------------------------
// K1: tiny setup. Build the 28 length-64 weight vectors:
//   rows r*3+c (r<8, c<3): u[r][c][o] = sum_i hv[c][i] * W[r][i][o]
//       where W[r] = sum_b w_comp[r,b] * bases[b],
//             hv[0]=W_in[0,:], hv[1]=W_in[1,:], hv[2]=b_in
//   rows 24..26: l[c][o] = sum_i hv[c][i] * loop_w[i][o]
//   row  27:     h_bias
// Also zeroes the global accumulators (must happen every launch).
// ---------------------------------------------------------------------------
__global__ void k_setup(const float* __restrict__ W_in, const float* __restrict__ b_in,
                        const float* __restrict__ w_comp, const float* __restrict__ bases,
                        const float* __restrict__ loop_w, const float* __restrict__ h_bias) {
    __shared__ float hv[3 * 64];
    __shared__ float t[3 * 4 * 64];   // t[c][b][o] = sum_i hv[c][i]*bases[b,i,o]
    int tid = threadIdx.x;
    if (tid < 2) g_acc[tid] = 0.0;

    for (int i = tid; i < 192; i += blockDim.x) {
        int c = i >> 6, o = i & 63;
        hv[i] = (c < 2) ? W_in[c * 64 + o] : b_in[o];
    }
    __syncthreads();

    for (int k = tid; k < 768; k += blockDim.x) {
        int c = k >> 8;            // /256
        int b = (k >> 6) & 3;
        int o = k & 63;
        float s = 0.f;
        #pragma unroll 8
        for (int i = 0; i < 64; i++)
            s += hv[c * 64 + i] * bases[b * 4096 + i * 64 + o];
        t[k] = s;
    }
    __syncthreads();

    // rows 0..23
    for (int k = tid; k < 24 * 64; k += blockDim.x) {
        int row = k >> 6, o = k & 63;
        int r = row / 3, c = row - r * 3;
        float s = 0.f;
        #pragma unroll
        for (int b = 0; b < 4; b++)
            s += w_comp[r * 4 + b] * t[(c * 4 + b) * 64 + o];
        g_Wt[k] = s;
    }
    // rows 24..27
    for (int k = tid; k < 4 * 64; k += blockDim.x) {
        int row = k >> 6, o = k & 63;
        float s;
        if (row < 3) {
            s = 0.f;
            #pragma unroll 8
            for (int i = 0; i < 64; i++)
                s += hv[row * 64 + i] * loop_w[i * 64 + o];
        } else {
            s = h_bias[o];
        }
        g_Wt[24 * 64 + k] = s;
    }
}

// ---------------------------------------------------------------------------
// Block-level double reduction, one atomicAdd per block.
// ---------------------------------------------------------------------------
__device__ __forceinline__ double block_reduce(double v) {
    __shared__ double sh[32];
    int lane = threadIdx.x & 31, wid = threadIdx.x >> 5;
    #pragma unroll
    for (int off = 16; off; off >>= 1) v += __shfl_down_sync(0xffffffffu, v, off);
    if (lane == 0) sh[wid] = v;
    __syncthreads();
    int nw = (blockDim.x + 31) >> 5;
    v = (threadIdx.x < nw) ? sh[threadIdx.x] : 0.0;
    if (wid == 0) {
        #pragma unroll
        for (int off = 16; off; off >>= 1) v += __shfl_down_sync(0xffffffffu, v, off);
    }
    return v;
}

// ---------------------------------------------------------------------------
// K2: per-node pass. One thread per node: 28 dots of F[n] (=fc_W row n)
// against the shared weight rows. Emits the float4 v-table for the edge pass
// and accumulates the self-loop + bias readout term.
// ---------------------------------------------------------------------------
__global__ void k_node(const float* __restrict__ fcW, const float2* __restrict__ feats) {
    __shared__ float4 ws[28 * 16];   // g_Wt viewed as float4[28][16]
    int tid = threadIdx.x;
    for (int i = tid; i < 28 * 16; i += blockDim.x)
        ws[i] = ((const float4*)g_Wt)[i];
    __syncthreads();

    int n = blockIdx.x * blockDim.x + tid;
    double contrib = 0.0;
    if (n < N_NODES) {
        const float4* F4 = (const float4*)(fcW + (size_t)n * 64);
        float acc[28];
        #pragma unroll
        for (int k = 0; k < 28; k++) acc[k] = 0.f;
        #pragma unroll 4
        for (int j = 0; j < 16; j++) {
            float4 f = F4[j];
            #pragma unroll
            for (int k = 0; k < 28; k++) {
                float4 w = ws[k * 16 + j];
                acc[k] += f.x * w.x + f.y * w.y + f.z * w.z + f.w * w.w;
            }
        }
        #pragma unroll
        for (int r = 0; r < 8; r++)
            g_vtab[n * 8 + r] = make_float4(acc[r * 3], acc[r * 3 + 1], acc[r * 3 + 2], 0.f);
        float2 f = feats[n];
        contrib = (double)(f.x * acc[24] + f.y * acc[25] + acc[26] + acc[27]);
    }
    double bs = block_reduce(contrib);
    if (threadIdx.x == 0) atomicAdd(&g_acc[0], bs);
}

// ---------------------------------------------------------------------------
// K3: edge pass. Streamed index reads + 2 random L2-resident sector reads
// per edge, 3 FMAs, global double reduction.
// ---------------------------------------------------------------------------
__global__ void k_edge(const int* __restrict__ src, const int* __restrict__ dst,
                       const int* __restrict__ et, const float2* __restrict__ feats,
                       int E) {
    double local = 0.0;
    int stride = gridDim.x * blockDim.x;
    for (int e = blockIdx.x * blockDim.x + threadIdx.x; e < E; e += stride) {
        int s = src[e], m = dst[e], r = et[e];
        float2 f = feats[s];
        float4 v = g_vtab[m * 8 + r];
        local += (double)fmaf(f.x, v.x, fmaf(f.y, v.y, v.z));
    }
    double bs = block_reduce(local);
    if (threadIdx.x == 0) atomicAdd(&g_acc[1], bs);
}

// ---------------------------------------------------------------------------
// K4: finalize — logit assembly + sigmoid.
// ---------------------------------------------------------------------------
__global__ void k_final(const float* __restrict__ fc_b, float* __restrict__ out) {
    double logit = g_acc[0] + g_acc[1] + (double)fc_b[0];
    out[0] = (float)(1.0 / (1.0 + exp(-logit)));
}

extern "C" void kernel_launch(void* const* d_in, const int* in_sizes, int n_in,
                              void* d_out, int out_size) {
    const float* features = (const float*)d_in[0];
    const int*   src      = (const int*)d_in[1];
    const int*   dst      = (const int*)d_in[2];
    const int*   etype    = (const int*)d_in[3];
    const float* W_in     = (const float*)d_in[4];
    const float* b_in     = (const float*)d_in[5];
    const float* w_comp   = (const float*)d_in[6];
    const float* bases    = (const float*)d_in[7];
    const float* loop_w   = (const float*)d_in[8];
    const float* h_bias   = (const float*)d_in[9];
    const float* fc_W     = (const float*)d_in[10];
    const float* fc_b     = (const float*)d_in[11];
    int E = in_sizes[1];

    k_setup<<<1, 256>>>(W_in, b_in, w_comp, bases, loop_w, h_bias);
    k_node<<<(N_NODES + 255) / 256, 256>>>(fc_W, (const float2*)features);
    k_edge<<<592, 256>>>(src, dst, etype, (const float2*)features, E);
    k_final<<<1, 1>>>(fc_b, (float*)d_out);
}

// round 2
// speedup vs baseline: 1.0426x; 1.0426x over previous
#include <cuda_runtime.h>
#include <math.h>

#define N_NODES 50000
#define HD      64
#define GRID    148
#define TPB     512

// Scratch (allocation-free: __device__ globals). All counters/accumulators are
// reset by the last-finishing block each launch -> deterministic across replays.
__device__ double   g_acc[2];
__device__ unsigned g_bar;
__device__ unsigned g_done;
__device__ float4   g_vtab[N_NODES * 8];   // per-(node, rel): (v0, v1, vb, 0)

__device__ __forceinline__ double block_reduce(double v) {
    __shared__ double sh[32];
    int lane = threadIdx.x & 31, wid = threadIdx.x >> 5;
    #pragma unroll
    for (int off = 16; off; off >>= 1) v += __shfl_down_sync(0xffffffffu, v, off);
    if (lane == 0) sh[wid] = v;
    __syncthreads();
    int nw = blockDim.x >> 5;
    v = (threadIdx.x < nw) ? sh[threadIdx.x] : 0.0;
    if (wid == 0) {
        #pragma unroll
        for (int off = 16; off; off >>= 1) v += __shfl_down_sync(0xffffffffu, v, off);
    }
    return v;
}

__global__ void __launch_bounds__(TPB, 1)
k_fused(const float2* __restrict__ feats,
        const int* __restrict__ src, const int* __restrict__ dst,
        const int* __restrict__ et,
        const float* __restrict__ W_in, const float* __restrict__ b_in,
        const float* __restrict__ w_comp, const float* __restrict__ bases,
        const float* __restrict__ loop_w, const float* __restrict__ h_bias,
        const float* __restrict__ fcW, const float* __restrict__ fc_b,
        int E, float* __restrict__ out)
{
    __shared__ float hv[3 * 64];
    __shared__ float t[3 * 4 * 64];          // t[c][b][o] = sum_i hv[c][i]*bases[b,i,o]
    __shared__ float4 ws[28 * 16];           // 28 weight rows [28][64] as float4
    float* wsf = (float*)ws;
    int tid = threadIdx.x;

    // ---- Phase A: every block builds the 28x64 weight table in SMEM ----
    for (int i = tid; i < 192; i += TPB) {
        int c = i >> 6, o = i & 63;
        hv[i] = (c < 2) ? W_in[c * 64 + o] : b_in[o];
    }
    __syncthreads();
    for (int k = tid; k < 768; k += TPB) {
        int c = k >> 8, b = (k >> 6) & 3, o = k & 63;
        float s = 0.f;
        #pragma unroll 8
        for (int i = 0; i < 64; i++)
            s += hv[c * 64 + i] * bases[b * 4096 + i * 64 + o];
        t[k] = s;
    }
    __syncthreads();
    // rows 0..23: u[r][c][o] = sum_b w_comp[r,b] * t[c][b][o]
    for (int k = tid; k < 24 * 64; k += TPB) {
        int row = k >> 6, o = k & 63;
        int r = row / 3, c = row - r * 3;
        float s = 0.f;
        #pragma unroll
        for (int b = 0; b < 4; b++)
            s += w_comp[r * 4 + b] * t[(c * 4 + b) * 64 + o];
        wsf[k] = s;
    }
    // rows 24..26: self-loop rows; row 27: h_bias
    for (int k = tid; k < 4 * 64; k += TPB) {
        int row = k >> 6, o = k & 63;
        float s;
        if (row < 3) {
            s = 0.f;
            #pragma unroll 8
            for (int i = 0; i < 64; i++)
                s += hv[row * 64 + i] * loop_w[i * 64 + o];
        } else {
            s = h_bias[o];
        }
        wsf[24 * 64 + k] = s;
    }
    __syncthreads();

    // ---- Phase B: node pass -> g_vtab + self-loop readout term ----
    double contrib = 0.0;
    for (int n = blockIdx.x * TPB + tid; n < N_NODES; n += GRID * TPB) {
        const float4* F4 = (const float4*)(fcW + (size_t)n * 64);
        float acc[28];
        #pragma unroll
        for (int k = 0; k < 28; k++) acc[k] = 0.f;
        #pragma unroll 4
        for (int j = 0; j < 16; j++) {
            float4 f = F4[j];
            #pragma unroll
            for (int k = 0; k < 28; k++) {
                float4 w = ws[k * 16 + j];
                acc[k] += f.x * w.x + f.y * w.y + f.z * w.z + f.w * w.w;
            }
        }
        #pragma unroll
        for (int r = 0; r < 8; r++)
            g_vtab[n * 8 + r] = make_float4(acc[r * 3], acc[r * 3 + 1], acc[r * 3 + 2], 0.f);
        float2 f = feats[n];
        contrib += (double)(f.x * acc[24] + f.y * acc[25] + acc[26] + acc[27]);
    }

    // ---- Grid barrier: vtab writes must be visible to all blocks ----
    __syncthreads();
    if (tid == 0) {
        __threadfence();
        atomicAdd(&g_bar, 1u);
        while (atomicAdd(&g_bar, 0u) < GRID) { }
    }
    __syncthreads();

    // ---- Phase C: edge pass (int4-vectorized indices, 4 edges/iter) ----
    int nvec = E >> 2;   // E is a multiple of 4 in this problem; tail handled below
    const int4* s4p = (const int4*)src;
    const int4* d4p = (const int4*)dst;
    const int4* r4p = (const int4*)et;
    for (int i = blockIdx.x * TPB + tid; i < nvec; i += GRID * TPB) {
        int4 s4 = s4p[i], d4 = d4p[i], r4 = r4p[i];
        float esum = 0.f;
        {
            float2 f = feats[s4.x]; float4 v = g_vtab[d4.x * 8 + r4.x];
            esum += fmaf(f.x, v.x, fmaf(f.y, v.y, v.z));
        }
        {
            float2 f = feats[s4.y]; float4 v = g_vtab[d4.y * 8 + r4.y];
            esum += fmaf(f.x, v.x, fmaf(f.y, v.y, v.z));
        }
        {
            float2 f = feats[s4.z]; float4 v = g_vtab[d4.z * 8 + r4.z];
            esum += fmaf(f.x, v.x, fmaf(f.y, v.y, v.z));
        }
        {
            float2 f = feats[s4.w]; float4 v = g_vtab[d4.w * 8 + r4.w];
            esum += fmaf(f.x, v.x, fmaf(f.y, v.y, v.z));
        }
        contrib += (double)esum;
    }
    // tail edges (if E not multiple of 4)
    for (int e = nvec * 4 + blockIdx.x * TPB + tid; e < E; e += GRID * TPB) {
        float2 f = feats[src[e]];
        float4 v = g_vtab[dst[e] * 8 + et[e]];
        contrib += (double)fmaf(f.x, v.x, fmaf(f.y, v.y, v.z));
    }

    // ---- Reduce + last-block finalize ----
    double bs = block_reduce(contrib);
    if (tid == 0) {
        atomicAdd(&g_acc[0], bs);
        __threadfence();
        unsigned d = atomicAdd(&g_done, 1u);
        if (d == GRID - 1) {
            double logit = atomicAdd(&g_acc[0], 0.0) + (double)fc_b[0];
            out[0] = (float)(1.0 / (1.0 + exp(-logit)));
            // reset state for the next (graph-replayed) launch
            g_acc[0] = 0.0; g_acc[1] = 0.0;
            g_bar = 0u; g_done = 0u;
        }
    }
}

extern "C" void kernel_launch(void* const* d_in, const int* in_sizes, int n_in,
                              void* d_out, int out_size) {
    const float* features = (const float*)d_in[0];
    const int*   src      = (const int*)d_in[1];
    const int*   dst      = (const int*)d_in[2];
    const int*   etype    = (const int*)d_in[3];
    const float* W_in     = (const float*)d_in[4];
    const float* b_in     = (const float*)d_in[5];
    const float* w_comp   = (const float*)d_in[6];
    const float* bases    = (const float*)d_in[7];
    const float* loop_w   = (const float*)d_in[8];
    const float* h_bias   = (const float*)d_in[9];
    const float* fc_W     = (const float*)d_in[10];
    const float* fc_b     = (const float*)d_in[11];
    int E = in_sizes[1];

    k_fused<<<GRID, TPB>>>((const float2*)features, src, dst, etype,
                           W_in, b_in, w_comp, bases, loop_w, h_bias,
                           fc_W, fc_b, E, (float*)d_out);
}